// round 15
// baseline (speedup 1.0000x reference)
#include <cuda_runtime.h>
#include <cstdint>

// Fixed problem shape
#define BB    8
#define HWPX  (512 * 512)
#define CC    64
#define SS    256

// Decomposition
#define NBLK  37                    // blocks per batch -> 296 = 2/SM, single wave
#define NPART (BB * NBLK)
#define P     32                    // pixels per stage (8 KB features)
#define NSTG  5
#define G_BASE 221                  // 8192 = 37*221 + 15
#define G_REM  15

#define NCW   16                    // consumer warps (label ranges of 16)
#define NWARPS (NCW + 2)            // + partition warp + producer warp
#define NTHR  (NWARPS * 32)         // 576

// SMEM layout (bytes) — label staging removed (labels come via LDG now)
#define OFF_ACC   0                                 // 65536  float2[256][32]
#define OFF_FEAT  (SS * CC * 4)                     // 65536, 5*8192 = 40960
#define OFF_LIST  (OFF_FEAT + NSTG * P * CC * 4)    // 106496, 5*16*32*2 = 5120
#define OFF_LCNT  (OFF_LIST + NSTG * NCW * 32 * 2)  // 111616, 320
#define OFF_SCNT  (OFF_LCNT + NSTG * NCW * 4)       // 111936, 1024
#define OFF_MBAR  (OFF_SCNT + SS * 4)               // 112960, 5*16 = 80
#define SMEM_TOTAL (OFF_MBAR + NSTG * 16)           // 113040 -> 2 CTAs/SM
#define STAGE_TX  (P * CC * 4)                      // 8192 (features only)

// L2-resident atomic accumulation buffers (zero-initialized at module load;
// mean_kernel re-zeros them after every read, so the invariant holds for
// every subsequent kernel_launch call / graph replay).
__device__ float4 g_sums4[BB * SS * CC / 4];   // 2 MB
__device__ float  g_cntg[BB * SS];             // 8 KB

// ---------- PTX helpers ----------
__device__ __forceinline__ uint32_t smem_u32(const void* p) {
    uint32_t a;
    asm("{ .reg .u64 t; cvta.to.shared.u64 t, %1; cvt.u32.u64 %0, t; }" : "=r"(a) : "l"(p));
    return a;
}
__device__ __forceinline__ void mbar_init(uint32_t a, uint32_t cnt) {
    asm volatile("mbarrier.init.shared.b64 [%0], %1;" :: "r"(a), "r"(cnt) : "memory");
}
__device__ __forceinline__ void mbar_expect_tx(uint32_t a, uint32_t bytes) {
    asm volatile("mbarrier.arrive.expect_tx.shared.b64 _, [%0], %1;" :: "r"(a), "r"(bytes) : "memory");
}
__device__ __forceinline__ void mbar_arrive(uint32_t a) {
    asm volatile("mbarrier.arrive.shared.b64 _, [%0];" :: "r"(a) : "memory");
}
__device__ __forceinline__ void mbar_wait_acq(uint32_t a, int ph) {
    asm volatile(
        "{\n\t.reg .pred p;\n\t"
        "WLA_%=:\n\t"
        "mbarrier.try_wait.parity.acquire.cta.shared::cta.b64 p, [%0], %1, 0x989680;\n\t"
        "@!p bra WLA_%=;\n\t}"
        :: "r"(a), "r"(ph) : "memory");
}
__device__ __forceinline__ void mbar_wait_rlx(uint32_t a, int ph) {
    asm volatile(
        "{\n\t.reg .pred p;\n\t"
        "WLR_%=:\n\t"
        "mbarrier.try_wait.parity.relaxed.cta.shared::cta.b64 p, [%0], %1, 0x989680;\n\t"
        "@!p bra WLR_%=;\n\t}"
        :: "r"(a), "r"(ph) : "memory");
}
__device__ __forceinline__ void bulk_g2s(uint32_t dst, const void* src, uint32_t bytes, uint32_t mbar) {
    asm volatile(
        "cp.async.bulk.shared::cluster.global.mbarrier::complete_tx::bytes [%0], [%1], %2, [%3];"
        :: "r"(dst), "l"(src), "r"(bytes), "r"(mbar) : "memory");
}
// Vector reduction (no return) to global: sm_90+ red.global.add.v4.f32
__device__ __forceinline__ void redg_add_v4(float4* p, float4 v) {
    asm volatile("red.global.add.v4.f32 [%0], {%1, %2, %3, %4};"
                 :: "l"(p), "f"(v.x), "f"(v.y), "f"(v.z), "f"(v.w) : "memory");
}
__device__ __forceinline__ void redg_add_f32(float* p, float v) {
    asm volatile("red.global.add.f32 [%0], %1;" :: "l"(p), "f"(v) : "memory");
}
// ----------------------------------

__global__ void __launch_bounds__(NTHR, 2)
pool_kernel(const float* __restrict__ feat, const int* __restrict__ lab) {
    extern __shared__ char smem[];
    float2*   acc2   = (float2*)(smem + OFF_ACC);          // [256][32] ch pairs
    float2*   sfeat2 = (float2*)(smem + OFF_FEAT);         // [NSTG*P][32]
    uint16_t* slist  = (uint16_t*)(smem + OFF_LIST);       // [NSTG*NCW][32]
    int*      slcnt  = (int*)(smem + OFF_LCNT);            // [NSTG*NCW]
    int*      scnt   = (int*)(smem + OFF_SCNT);            // [SS]
    const uint32_t sb = smem_u32(smem);

    const int tid  = threadIdx.x;
    const int wid  = tid >> 5;
    const int lane = tid & 31;

    if (tid == 0) {
        #pragma unroll
        for (int s = 0; s < NSTG; s++) {
            // full: producer expect_tx (features) + partition arrive (lists) = 2
            mbar_init(sb + OFF_MBAR + s * 16,     2);
            // empty: the 16 consumer warps arrive
            mbar_init(sb + OFF_MBAR + s * 16 + 8, NCW);
        }
    }
    __syncthreads();   // mbars visible before any TMA / arrives

    const int bidx = blockIdx.x;
    const int b = bidx / NBLK;
    const int j = bidx % NBLK;
    const int ng     = G_BASE + (j < G_REM ? 1 : 0);
    const int base_g = j * G_BASE + (j < G_REM ? j : G_REM);

    const float* f = feat + (size_t)b * HWPX * CC;
    const int*   l = lab  + (size_t)b * HWPX;

    if (wid < NCW) {
        // ---- consumers: warp w owns labels [w*16, w*16+16), float2 per lane ----
        // Zero OWN accumulator rows (race-free), overlapped with first TMA.
        {
            float2 z = make_float2(0.f, 0.f);
            float2* arow = &acc2[(wid * 16) * 32 + lane];
            #pragma unroll
            for (int r = 0; r < 16; r++) arow[r * 32] = z;
        }
        int ph = 0, s = 0;
        for (int g = 0; g < ng; g++) {
            // ONE wait: full = features landed (tx) AND lists written (partition)
            mbar_wait_acq(sb + OFF_MBAR + s * 16, ph);
            const int n = slcnt[s * NCW + wid];                  // broadcast
            const uint16_t* lst = slist + (s * NCW + wid) * 32;
            const float2*   sf  = sfeat2 + (size_t)s * P * 32;
            for (int k = 0; k < n; k++) {
                const uint32_t e  = lst[k];                      // broadcast LDS.16
                const int lb = e & 255;
                const int i  = e >> 8;
                const float2 v = sf[i * 32 + lane];
                float2* a = &acc2[lb * 32 + lane];
                float2 av = *a;
                av.x += v.x; av.y += v.y;
                *a = av;
            }
            if (lane == 0) mbar_arrive(sb + OFF_MBAR + s * 16 + 8);  // empty
            if (++s == NSTG) { s = 0; ph ^= 1; }
        }
    } else if (wid == NCW) {
        // ---- partition warp: labels via coalesced LDG (prefetched 1 stage
        //      ahead), buckets by label>>4, lists written under empty-wait,
        //      then arrives on FULL (count 2 of 2) ----
        #pragma unroll
        for (int i = lane; i < SS; i += 32) scnt[i] = 0;         // own the counts
        int ph = 1, s = 0;
        int lbl = __ldg(l + (size_t)base_g * P + lane);          // stage 0 labels
        for (int g = 0; g < ng; g++) {
            int lbl_next = 0;
            if (g + 1 < ng)                                      // prefetch next
                lbl_next = __ldg(l + (size_t)(base_g + g + 1) * P + lane);
            mbar_wait_rlx(sb + OFF_MBAR + s * 16 + 8, ph);       // slot empty
            const int bucket = lbl >> 4;
            const unsigned same = __match_any_sync(0xffffffffu, bucket);
            const int pos = __popc(same & ((1u << lane) - 1u));
            const int cnt = __popc(same);
            if (lane < NCW) slcnt[s * NCW + lane] = 0;
            __syncwarp();
            slist[(s * NCW + bucket) * 32 + pos] = (uint16_t)(lbl | (lane << 8));
            if (pos == 0) slcnt[s * NCW + bucket] = cnt;
            atomicAdd(&scnt[lbl], 1);
            __syncwarp();
            if (lane == 0) mbar_arrive(sb + OFF_MBAR + s * 16);  // full (lists)
            lbl = lbl_next;
            if (++s == NSTG) { s = 0; ph ^= 1; }
        }
    } else if (tid == NCW * 32 + 32) {
        // ---- producer thread: single 8 KB feature TMA per stage ----
        int ph = 1, s = 0;
        for (int g = 0; g < ng; g++) {
            mbar_wait_rlx(sb + OFF_MBAR + s * 16 + 8, ph);       // empty
            const uint32_t ful = sb + OFF_MBAR + s * 16;
            mbar_expect_tx(ful, STAGE_TX);
            const size_t pix0 = (size_t)(base_g + g) * P;
            bulk_g2s(sb + OFF_FEAT + s * (P * CC * 4), f + pix0 * CC, P * CC * 4, ful);
            if (++s == NSTG) { s = 0; ph ^= 1; }
        }
    }

    __syncthreads();

    // Flush into L2-resident final buffer via vector REDG (no DRAM scratch).
    // Plain constant-stride order: same-address REDGs from peer CTAs merge
    // cheaply at the LTS (0.854 cyc/lane single-addr) — do NOT decollide.
    float4* acc4 = (float4*)acc2;
    float4* gs = g_sums4 + (size_t)b * (SS * CC / 4);
    #pragma unroll
    for (int i = tid; i < SS * CC / 4; i += NTHR) redg_add_v4(&gs[i], acc4[i]);
    float* gc = g_cntg + b * SS;
    for (int i = tid; i < SS; i += NTHR) redg_add_f32(&gc[i], (float)scnt[i]);

    // PDL signal at the very end (proven position: earlier signaling lets
    // dependent CTAs become resident mid-pool and costs ~40us).
    asm volatile("griddepcontrol.launch_dependents;");
}

// Finalize: pure L2 traffic. Launched with PDL — prologue overlaps the pool
// tail; griddepcontrol.wait blocks until pool's memory flush completes
// (no-op if launched without PDL).
__global__ void __launch_bounds__(256)
mean_kernel(float4* __restrict__ out4) {
    const int i4 = blockIdx.x * 256 + threadIdx.x;      // 0 .. 32767
    const int PER_B4 = SS * CC / 4;                     // 4096
    const int b   = i4 / PER_B4;
    const int sc4 = i4 - b * PER_B4;
    const int s   = sc4 >> 4;                           // 16 float4 per segment

    asm volatile("griddepcontrol.wait;" ::: "memory");

    const float4 v = g_sums4[i4];
    const float  c = g_cntg[b * SS + s];
    const float inv = 1.0f / fmaxf(c, 1.0f);
    out4[i4] = make_float4(v.x * inv, v.y * inv, v.z * inv, v.w * inv);
    g_sums4[i4] = make_float4(0.f, 0.f, 0.f, 0.f);

    __syncthreads();   // all 16 readers of this segment's count are in this block
    if ((sc4 & 15) == 0) g_cntg[b * SS + s] = 0.0f;
}

extern "C" void kernel_launch(void* const* d_in, const int* in_sizes, int n_in,
                              void* d_out, int out_size) {
    const float* feat = (const float*)d_in[0];
    const int*   lab  = (const int*)d_in[1];
    float4*      out4 = (float4*)d_out;

    cudaFuncSetAttribute(pool_kernel,
                         cudaFuncAttributeMaxDynamicSharedMemorySize,
                         (int)SMEM_TOTAL);

    pool_kernel<<<NPART, NTHR, SMEM_TOTAL>>>(feat, lab);

    const int n4 = BB * SS * CC / 4;                    // 32768

    // PDL launch of the finalize kernel; fall back to a plain launch if the
    // attributed launch is not accepted (wait is then a no-op -> still correct).
    cudaLaunchConfig_t cfg = {};
    cfg.gridDim  = dim3(n4 / 256);
    cfg.blockDim = dim3(256);
    cudaLaunchAttribute attr[1];
    attr[0].id = cudaLaunchAttributeProgrammaticStreamSerialization;
    attr[0].val.programmaticStreamSerializationAllowed = 1;
    cfg.attrs = attr;
    cfg.numAttrs = 1;
    cudaError_t e = cudaLaunchKernelEx(&cfg, mean_kernel, out4);
    if (e != cudaSuccess) {
        mean_kernel<<<n4 / 256, 256>>>(out4);
    }
}

// round 16
// speedup vs baseline: 1.1149x; 1.1149x over previous
#include <cuda_runtime.h>
#include <cstdint>

// Fixed problem shape
#define BB    8
#define HWPX  (512 * 512)
#define CC    64
#define SS    256

// Decomposition
#define NBLK  37                    // blocks per batch -> 296 = 2/SM, single wave
#define NPART (BB * NBLK)
#define P     32                    // pixels per stage (8 KB features)
#define NSTG  5
#define G_BASE 221                  // 8192 = 37*221 + 15
#define G_REM  15

#define NCW   16                    // consumer warps (label ranges of 16)
#define NWARPS (NCW + 2)            // + partition warp + producer warp
#define NTHR  (NWARPS * 32)         // 576

// SMEM layout (bytes)
#define OFF_ACC   0                                 // 65536  float2[256][32]
#define OFF_FEAT  (SS * CC * 4)                     // 65536, 5*8192 = 40960
#define OFF_LAB   (OFF_FEAT + NSTG * P * CC * 4)    // 106496, 640
#define OFF_LIST  (OFF_LAB + NSTG * P * 4)          // 107136, 5*16*32*2 = 5120
#define OFF_LCNT  (OFF_LIST + NSTG * NCW * 32 * 2)  // 112256, 320
#define OFF_SCNT  (OFF_LCNT + NSTG * NCW * 4)       // 112576, 1024
#define OFF_MBAR  (OFF_SCNT + SS * 4)               // 113600, 5*24 = 120
#define SMEM_TOTAL (OFF_MBAR + NSTG * 24)           // 113720 -> 2 CTAs/SM
#define STAGE_TX  (P * CC * 4 + P * 4)              // 8320

// L2-resident atomic accumulation buffers (zero-initialized at module load;
// mean_kernel re-zeros them after every read, so the invariant holds for
// every subsequent kernel_launch call / graph replay).
__device__ float4 g_sums4[BB * SS * CC / 4];   // 2 MB
__device__ float  g_cntg[BB * SS];             // 8 KB

// ---------- PTX helpers ----------
__device__ __forceinline__ uint32_t smem_u32(const void* p) {
    uint32_t a;
    asm("{ .reg .u64 t; cvta.to.shared.u64 t, %1; cvt.u32.u64 %0, t; }" : "=r"(a) : "l"(p));
    return a;
}
__device__ __forceinline__ void mbar_init(uint32_t a, uint32_t cnt) {
    asm volatile("mbarrier.init.shared.b64 [%0], %1;" :: "r"(a), "r"(cnt) : "memory");
}
__device__ __forceinline__ void mbar_expect_tx(uint32_t a, uint32_t bytes) {
    asm volatile("mbarrier.arrive.expect_tx.shared.b64 _, [%0], %1;" :: "r"(a), "r"(bytes) : "memory");
}
__device__ __forceinline__ void mbar_arrive(uint32_t a) {
    asm volatile("mbarrier.arrive.shared.b64 _, [%0];" :: "r"(a) : "memory");
}
__device__ __forceinline__ void mbar_wait_acq(uint32_t a, int ph) {
    asm volatile(
        "{\n\t.reg .pred p;\n\t"
        "WLA_%=:\n\t"
        "mbarrier.try_wait.parity.acquire.cta.shared::cta.b64 p, [%0], %1, 0x989680;\n\t"
        "@!p bra WLA_%=;\n\t}"
        :: "r"(a), "r"(ph) : "memory");
}
__device__ __forceinline__ void mbar_wait_rlx(uint32_t a, int ph) {
    asm volatile(
        "{\n\t.reg .pred p;\n\t"
        "WLR_%=:\n\t"
        "mbarrier.try_wait.parity.relaxed.cta.shared::cta.b64 p, [%0], %1, 0x989680;\n\t"
        "@!p bra WLR_%=;\n\t}"
        :: "r"(a), "r"(ph) : "memory");
}
__device__ __forceinline__ void bulk_g2s(uint32_t dst, const void* src, uint32_t bytes, uint32_t mbar) {
    asm volatile(
        "cp.async.bulk.shared::cluster.global.mbarrier::complete_tx::bytes [%0], [%1], %2, [%3];"
        :: "r"(dst), "l"(src), "r"(bytes), "r"(mbar) : "memory");
}
// Vector reduction (no return) to global: sm_90+ red.global.add.v4.f32
__device__ __forceinline__ void redg_add_v4(float4* p, float4 v) {
    asm volatile("red.global.add.v4.f32 [%0], {%1, %2, %3, %4};"
                 :: "l"(p), "f"(v.x), "f"(v.y), "f"(v.z), "f"(v.w) : "memory");
}
__device__ __forceinline__ void redg_add_f32(float* p, float v) {
    asm volatile("red.global.add.f32 [%0], %1;" :: "l"(p), "f"(v) : "memory");
}
// ----------------------------------

__global__ void __launch_bounds__(NTHR, 2)
pool_kernel(const float* __restrict__ feat, const int* __restrict__ lab) {
    extern __shared__ char smem[];
    float2*   acc2   = (float2*)(smem + OFF_ACC);          // [256][32] ch pairs
    float2*   sfeat2 = (float2*)(smem + OFF_FEAT);         // [NSTG*P][32]
    int*      slab   = (int*)(smem + OFF_LAB);             // [NSTG*P]
    uint16_t* slist  = (uint16_t*)(smem + OFF_LIST);       // [NSTG*NCW][32]
    int*      slcnt  = (int*)(smem + OFF_LCNT);            // [NSTG*NCW]
    int*      scnt   = (int*)(smem + OFF_SCNT);            // [SS]
    const uint32_t sb = smem_u32(smem);

    const int tid  = threadIdx.x;
    const int wid  = tid >> 5;
    const int lane = tid & 31;

    if (tid == 0) {
        #pragma unroll
        for (int s = 0; s < NSTG; s++) {
            mbar_init(sb + OFF_MBAR + s * 24,      1);        // full (tx-based)
            mbar_init(sb + OFF_MBAR + s * 24 + 8,  1);        // ready (partition lane0)
            mbar_init(sb + OFF_MBAR + s * 24 + 16, NCW + 1);  // empty (consumers + partition)
        }
    }
    __syncthreads();   // mbars visible to producer before any TMA

    const int bidx = blockIdx.x;
    const int b = bidx / NBLK;
    const int j = bidx % NBLK;
    const int ng     = G_BASE + (j < G_REM ? 1 : 0);
    const int base_g = j * G_BASE + (j < G_REM ? j : G_REM);

    const float* f = feat + (size_t)b * HWPX * CC;
    const int*   l = lab  + (size_t)b * HWPX;

    if (wid < NCW) {
        // ---- consumers: warp w owns labels [w*16, w*16+16), float2 per lane ----
        // Zero OWN accumulator rows (race-free: only this warp touches them),
        // overlapped with the producer's first TMA in flight.
        {
            float2 z = make_float2(0.f, 0.f);
            float2* arow = &acc2[(wid * 16) * 32 + lane];
            #pragma unroll
            for (int r = 0; r < 16; r++) arow[r * 32] = z;
        }
        int ph = 0, s = 0;
        for (int g = 0; g < ng; g++) {
            mbar_wait_acq(sb + OFF_MBAR + s * 24 + 8, ph);       // ready
            const int n = slcnt[s * NCW + wid];                  // broadcast
            const uint16_t* lst = slist + (s * NCW + wid) * 32;
            const float2*   sf  = sfeat2 + (size_t)s * P * 32;
            for (int k = 0; k < n; k++) {
                const uint32_t e  = lst[k];                      // broadcast LDS.16
                const int lb = e & 255;
                const int i  = e >> 8;
                const float2 v = sf[i * 32 + lane];
                float2* a = &acc2[lb * 32 + lane];
                float2 av = *a;
                av.x += v.x; av.y += v.y;
                *a = av;
            }
            if (lane == 0) mbar_arrive(sb + OFF_MBAR + s * 24 + 16);
            if (++s == NSTG) { s = 0; ph ^= 1; }
        }
    } else if (wid == NCW) {
        // ---- partition warp: bucket the 32 pixels of each stage by label>>4 ----
        #pragma unroll
        for (int i = lane; i < SS; i += 32) scnt[i] = 0;         // own the counts
        int ph = 0, s = 0;
        for (int g = 0; g < ng; g++) {
            mbar_wait_acq(sb + OFF_MBAR + s * 24, ph);           // full
            const int lb = slab[s * P + lane];
            const int bucket = lb >> 4;
            const unsigned same = __match_any_sync(0xffffffffu, bucket);
            const int pos = __popc(same & ((1u << lane) - 1u));
            const int cnt = __popc(same);
            if (lane < NCW) slcnt[s * NCW + lane] = 0;
            __syncwarp();
            slist[(s * NCW + bucket) * 32 + pos] = (uint16_t)(lb | (lane << 8));
            if (pos == 0) slcnt[s * NCW + bucket] = cnt;
            atomicAdd(&scnt[lb], 1);
            __syncwarp();
            if (lane == 0) {
                mbar_arrive(sb + OFF_MBAR + s * 24 + 8);         // ready
                mbar_arrive(sb + OFF_MBAR + s * 24 + 16);        // empty (labels done)
            }
            if (++s == NSTG) { s = 0; ph ^= 1; }
        }
    } else if (tid == NCW * 32 + 32) {
        // ---- producer thread: starts immediately after mbar-init sync ----
        int ph = 1, s = 0;
        for (int g = 0; g < ng; g++) {
            mbar_wait_rlx(sb + OFF_MBAR + s * 24 + 16, ph);      // empty
            const uint32_t ful = sb + OFF_MBAR + s * 24;
            mbar_expect_tx(ful, STAGE_TX);
            const size_t pix0 = (size_t)(base_g + g) * P;
            bulk_g2s(sb + OFF_FEAT + s * (P * CC * 4), f + pix0 * CC, P * CC * 4, ful);
            bulk_g2s(sb + OFF_LAB  + s * (P * 4),      l + pix0,      P * 4,      ful);
            if (++s == NSTG) { s = 0; ph ^= 1; }
        }
    }

    __syncthreads();

    // Flush into L2-resident final buffer via vector REDG (no DRAM scratch).
    // Plain constant-stride order: same-address REDGs from peer CTAs merge
    // cheaply at the LTS (0.854 cyc/lane single-addr) — do NOT decollide.
    float4* acc4 = (float4*)acc2;
    float4* gs = g_sums4 + (size_t)b * (SS * CC / 4);
    #pragma unroll
    for (int i = tid; i < SS * CC / 4; i += NTHR) redg_add_v4(&gs[i], acc4[i]);
    float* gc = g_cntg + b * SS;
    for (int i = tid; i < SS; i += NTHR) redg_add_f32(&gc[i], (float)scnt[i]);

    // PDL signal at the very end (proven position: earlier signaling lets
    // dependent CTAs become resident mid-pool and costs ~40us).
    asm volatile("griddepcontrol.launch_dependents;");
}

// Finalize: pure L2 traffic. Launched with PDL — prologue overlaps the pool
// tail; griddepcontrol.wait blocks until pool's memory flush completes
// (no-op if launched without PDL).
__global__ void __launch_bounds__(256)
mean_kernel(float4* __restrict__ out4) {
    const int i4 = blockIdx.x * 256 + threadIdx.x;      // 0 .. 32767
    const int PER_B4 = SS * CC / 4;                     // 4096
    const int b   = i4 / PER_B4;
    const int sc4 = i4 - b * PER_B4;
    const int s   = sc4 >> 4;                           // 16 float4 per segment

    asm volatile("griddepcontrol.wait;" ::: "memory");

    const float4 v = g_sums4[i4];
    const float  c = g_cntg[b * SS + s];
    const float inv = 1.0f / fmaxf(c, 1.0f);
    out4[i4] = make_float4(v.x * inv, v.y * inv, v.z * inv, v.w * inv);
    g_sums4[i4] = make_float4(0.f, 0.f, 0.f, 0.f);

    __syncthreads();   // all 16 readers of this segment's count are in this block
    if ((sc4 & 15) == 0) g_cntg[b * SS + s] = 0.0f;
}

extern "C" void kernel_launch(void* const* d_in, const int* in_sizes, int n_in,
                              void* d_out, int out_size) {
    const float* feat = (const float*)d_in[0];
    const int*   lab  = (const int*)d_in[1];
    float4*      out4 = (float4*)d_out;

    cudaFuncSetAttribute(pool_kernel,
                         cudaFuncAttributeMaxDynamicSharedMemorySize,
                         (int)SMEM_TOTAL);

    pool_kernel<<<NPART, NTHR, SMEM_TOTAL>>>(feat, lab);

    const int n4 = BB * SS * CC / 4;                    // 32768

    // PDL launch of the finalize kernel; fall back to a plain launch if the
    // attributed launch is not accepted (wait is then a no-op -> still correct).
    cudaLaunchConfig_t cfg = {};
    cfg.gridDim  = dim3(n4 / 256);
    cfg.blockDim = dim3(256);
    cudaLaunchAttribute attr[1];
    attr[0].id = cudaLaunchAttributeProgrammaticStreamSerialization;
    attr[0].val.programmaticStreamSerializationAllowed = 1;
    cfg.attrs = attr;
    cfg.numAttrs = 1;
    cudaError_t e = cudaLaunchKernelEx(&cfg, mean_kernel, out4);
    if (e != cudaSuccess) {
        mean_kernel<<<n4 / 256, 256>>>(out4);
    }
}

// round 17
// speedup vs baseline: 1.1198x; 1.0044x over previous
#include <cuda_runtime.h>
#include <cstdint>

// Fixed problem shape
#define BB    8
#define HWPX  (512 * 512)
#define CC    64
#define SS    256

// Decomposition
#define NBLK  37                    // blocks per batch -> 296 = 2/SM, single wave
#define NPART (BB * NBLK)
#define P     32                    // pixels per stage (8 KB features)
#define NSTG  5
#define G_BASE 221                  // 8192 = 37*221 + 15
#define G_REM  15

#define NCW   16                    // consumer warps (label ranges of 16)
#define NWARPS (NCW + 2)            // + partition warp + producer warp
#define NTHR  (NWARPS * 32)         // 576

// SMEM layout (bytes)
#define OFF_ACC   0                                 // 65536  float2[256][32]
#define OFF_FEAT  (SS * CC * 4)                     // 65536, 5*8192 = 40960
#define OFF_LAB   (OFF_FEAT + NSTG * P * CC * 4)    // 106496, 640
#define OFF_LIST  (OFF_LAB + NSTG * P * 4)          // 107136, 5*16*32*2 = 5120
#define OFF_LCNT  (OFF_LIST + NSTG * NCW * 32 * 2)  // 112256, 320
#define OFF_SCNT  (OFF_LCNT + NSTG * NCW * 4)       // 112576, 1024
#define OFF_MBAR  (OFF_SCNT + SS * 4)               // 113600, 5*24 = 120
#define SMEM_TOTAL (OFF_MBAR + NSTG * 24)           // 113720 -> 2 CTAs/SM
#define STAGE_TX  (P * CC * 4 + P * 4)              // 8320

// L2-resident atomic accumulation buffers (zero-initialized at module load;
// mean_kernel re-zeros them after every read, so the invariant holds for
// every subsequent kernel_launch call / graph replay).
__device__ float4 g_sums4[BB * SS * CC / 4];   // 2 MB
__device__ float  g_cntg[BB * SS];             // 8 KB

// ---------- PTX helpers ----------
__device__ __forceinline__ uint32_t smem_u32(const void* p) {
    uint32_t a;
    asm("{ .reg .u64 t; cvta.to.shared.u64 t, %1; cvt.u32.u64 %0, t; }" : "=r"(a) : "l"(p));
    return a;
}
__device__ __forceinline__ void mbar_init(uint32_t a, uint32_t cnt) {
    asm volatile("mbarrier.init.shared.b64 [%0], %1;" :: "r"(a), "r"(cnt) : "memory");
}
__device__ __forceinline__ void mbar_expect_tx(uint32_t a, uint32_t bytes) {
    asm volatile("mbarrier.arrive.expect_tx.shared.b64 _, [%0], %1;" :: "r"(a), "r"(bytes) : "memory");
}
__device__ __forceinline__ void mbar_arrive(uint32_t a) {
    asm volatile("mbarrier.arrive.shared.b64 _, [%0];" :: "r"(a) : "memory");
}
__device__ __forceinline__ void mbar_wait_acq(uint32_t a, int ph) {
    asm volatile(
        "{\n\t.reg .pred p;\n\t"
        "WLA_%=:\n\t"
        "mbarrier.try_wait.parity.acquire.cta.shared::cta.b64 p, [%0], %1, 0x989680;\n\t"
        "@!p bra WLA_%=;\n\t}"
        :: "r"(a), "r"(ph) : "memory");
}
__device__ __forceinline__ void mbar_wait_rlx(uint32_t a, int ph) {
    asm volatile(
        "{\n\t.reg .pred p;\n\t"
        "WLR_%=:\n\t"
        "mbarrier.try_wait.parity.relaxed.cta.shared::cta.b64 p, [%0], %1, 0x989680;\n\t"
        "@!p bra WLR_%=;\n\t}"
        :: "r"(a), "r"(ph) : "memory");
}
__device__ __forceinline__ void bulk_g2s(uint32_t dst, const void* src, uint32_t bytes, uint32_t mbar) {
    asm volatile(
        "cp.async.bulk.shared::cluster.global.mbarrier::complete_tx::bytes [%0], [%1], %2, [%3];"
        :: "r"(dst), "l"(src), "r"(bytes), "r"(mbar) : "memory");
}
// Vector reduction (no return) to global: sm_90+ red.global.add.v4.f32
__device__ __forceinline__ void redg_add_v4(float4* p, float4 v) {
    asm volatile("red.global.add.v4.f32 [%0], {%1, %2, %3, %4};"
                 :: "l"(p), "f"(v.x), "f"(v.y), "f"(v.z), "f"(v.w) : "memory");
}
__device__ __forceinline__ void redg_add_f32(float* p, float v) {
    asm volatile("red.global.add.f32 [%0], %1;" :: "l"(p), "f"(v) : "memory");
}
// ----------------------------------

__global__ void __launch_bounds__(NTHR, 2)
pool_kernel(const float* __restrict__ feat, const int* __restrict__ lab) {
    extern __shared__ char smem[];
    float2*   acc2   = (float2*)(smem + OFF_ACC);          // [256][32] ch pairs
    float2*   sfeat2 = (float2*)(smem + OFF_FEAT);         // [NSTG*P][32]
    int*      slab   = (int*)(smem + OFF_LAB);             // [NSTG*P]
    uint16_t* slist  = (uint16_t*)(smem + OFF_LIST);       // [NSTG*NCW][32]
    int*      slcnt  = (int*)(smem + OFF_LCNT);            // [NSTG*NCW]
    int*      scnt   = (int*)(smem + OFF_SCNT);            // [SS]
    const uint32_t sb = smem_u32(smem);

    const int tid  = threadIdx.x;
    const int wid  = tid >> 5;
    const int lane = tid & 31;

    if (tid == 0) {
        #pragma unroll
        for (int s = 0; s < NSTG; s++) {
            mbar_init(sb + OFF_MBAR + s * 24,      1);        // full (tx-based)
            mbar_init(sb + OFF_MBAR + s * 24 + 8,  1);        // ready (partition lane0)
            mbar_init(sb + OFF_MBAR + s * 24 + 16, NCW + 1);  // empty (consumers + partition)
        }
    }
    __syncthreads();   // mbars visible to producer before any TMA

    const int bidx = blockIdx.x;
    const int b = bidx / NBLK;
    const int j = bidx % NBLK;
    const int ng     = G_BASE + (j < G_REM ? 1 : 0);
    const int base_g = j * G_BASE + (j < G_REM ? j : G_REM);

    const float* f = feat + (size_t)b * HWPX * CC;
    const int*   l = lab  + (size_t)b * HWPX;

    if (wid < NCW) {
        // ---- consumers: warp w owns labels [w*16, w*16+16), float2 per lane ----
        // Zero OWN accumulator rows (race-free: only this warp touches them),
        // overlapped with the producer's first TMA in flight.
        {
            float2 z = make_float2(0.f, 0.f);
            float2* arow = &acc2[(wid * 16) * 32 + lane];
            #pragma unroll
            for (int r = 0; r < 16; r++) arow[r * 32] = z;
        }
        // 64-bit views for packed f32x2 accumulate (LDS.64 / ADD.F32X2 / STS.64)
        unsigned long long* acc64 = (unsigned long long*)acc2;
        int ph = 0, s = 0;
        for (int g = 0; g < ng; g++) {
            mbar_wait_acq(sb + OFF_MBAR + s * 24 + 8, ph);       // ready
            const int n = slcnt[s * NCW + wid];                  // broadcast
            const uint16_t* lst = slist + (s * NCW + wid) * 32;
            const unsigned long long* sf64 =
                (const unsigned long long*)(sfeat2 + (size_t)s * P * 32);
            for (int k = 0; k < n; k++) {
                const uint32_t e  = lst[k];                      // broadcast LDS.16
                const int lb = e & 255;
                const int i  = e >> 8;
                const unsigned long long v = sf64[i * 32 + lane];
                unsigned long long av = acc64[lb * 32 + lane];
                unsigned long long r;
                asm("add.rn.f32x2 %0, %1, %2;" : "=l"(r) : "l"(av), "l"(v));
                acc64[lb * 32 + lane] = r;
            }
            if (lane == 0) mbar_arrive(sb + OFF_MBAR + s * 24 + 16);
            if (++s == NSTG) { s = 0; ph ^= 1; }
        }
    } else if (wid == NCW) {
        // ---- partition warp: bucket the 32 pixels of each stage by label>>4 ----
        #pragma unroll
        for (int i = lane; i < SS; i += 32) scnt[i] = 0;         // own the counts
        int ph = 0, s = 0;
        for (int g = 0; g < ng; g++) {
            mbar_wait_acq(sb + OFF_MBAR + s * 24, ph);           // full
            const int lb = slab[s * P + lane];
            const int bucket = lb >> 4;
            const unsigned same = __match_any_sync(0xffffffffu, bucket);
            const int pos = __popc(same & ((1u << lane) - 1u));
            const int cnt = __popc(same);
            if (lane < NCW) slcnt[s * NCW + lane] = 0;
            __syncwarp();
            slist[(s * NCW + bucket) * 32 + pos] = (uint16_t)(lb | (lane << 8));
            if (pos == 0) slcnt[s * NCW + bucket] = cnt;
            atomicAdd(&scnt[lb], 1);
            __syncwarp();
            if (lane == 0) {
                mbar_arrive(sb + OFF_MBAR + s * 24 + 8);         // ready
                mbar_arrive(sb + OFF_MBAR + s * 24 + 16);        // empty (labels done)
            }
            if (++s == NSTG) { s = 0; ph ^= 1; }
        }
    } else if (tid == NCW * 32 + 32) {
        // ---- producer thread: starts immediately after mbar-init sync ----
        int ph = 1, s = 0;
        for (int g = 0; g < ng; g++) {
            mbar_wait_rlx(sb + OFF_MBAR + s * 24 + 16, ph);      // empty
            const uint32_t ful = sb + OFF_MBAR + s * 24;
            mbar_expect_tx(ful, STAGE_TX);
            const size_t pix0 = (size_t)(base_g + g) * P;
            bulk_g2s(sb + OFF_FEAT + s * (P * CC * 4), f + pix0 * CC, P * CC * 4, ful);
            bulk_g2s(sb + OFF_LAB  + s * (P * 4),      l + pix0,      P * 4,      ful);
            if (++s == NSTG) { s = 0; ph ^= 1; }
        }
    }

    __syncthreads();

    // Flush into L2-resident final buffer via vector REDG (no DRAM scratch).
    // Plain constant-stride order: same-address REDGs from peer CTAs merge
    // cheaply at the LTS (0.854 cyc/lane single-addr) — do NOT decollide.
    float4* acc4 = (float4*)acc2;
    float4* gs = g_sums4 + (size_t)b * (SS * CC / 4);
    #pragma unroll
    for (int i = tid; i < SS * CC / 4; i += NTHR) redg_add_v4(&gs[i], acc4[i]);
    float* gc = g_cntg + b * SS;
    for (int i = tid; i < SS; i += NTHR) redg_add_f32(&gc[i], (float)scnt[i]);

    // PDL signal at the very end (proven position: earlier signaling lets
    // dependent CTAs become resident mid-pool and costs ~40us).
    asm volatile("griddepcontrol.launch_dependents;");
}

// Finalize: pure L2 traffic. Launched with PDL — prologue overlaps the pool
// tail; griddepcontrol.wait blocks until pool's memory flush completes
// (no-op if launched without PDL).
__global__ void __launch_bounds__(256)
mean_kernel(float4* __restrict__ out4) {
    const int i4 = blockIdx.x * 256 + threadIdx.x;      // 0 .. 32767
    const int PER_B4 = SS * CC / 4;                     // 4096
    const int b   = i4 / PER_B4;
    const int sc4 = i4 - b * PER_B4;
    const int s   = sc4 >> 4;                           // 16 float4 per segment

    asm volatile("griddepcontrol.wait;" ::: "memory");

    const float4 v = g_sums4[i4];
    const float  c = g_cntg[b * SS + s];
    const float inv = 1.0f / fmaxf(c, 1.0f);
    out4[i4] = make_float4(v.x * inv, v.y * inv, v.z * inv, v.w * inv);
    g_sums4[i4] = make_float4(0.f, 0.f, 0.f, 0.f);

    __syncthreads();   // all 16 readers of this segment's count are in this block
    if ((sc4 & 15) == 0) g_cntg[b * SS + s] = 0.0f;
}

extern "C" void kernel_launch(void* const* d_in, const int* in_sizes, int n_in,
                              void* d_out, int out_size) {
    const float* feat = (const float*)d_in[0];
    const int*   lab  = (const int*)d_in[1];
    float4*      out4 = (float4*)d_out;

    cudaFuncSetAttribute(pool_kernel,
                         cudaFuncAttributeMaxDynamicSharedMemorySize,
                         (int)SMEM_TOTAL);

    pool_kernel<<<NPART, NTHR, SMEM_TOTAL>>>(feat, lab);

    const int n4 = BB * SS * CC / 4;                    // 32768

    // PDL launch of the finalize kernel; fall back to a plain launch if the
    // attributed launch is not accepted (wait is then a no-op -> still correct).
    cudaLaunchConfig_t cfg = {};
    cfg.gridDim  = dim3(n4 / 256);
    cfg.blockDim = dim3(256);
    cudaLaunchAttribute attr[1];
    attr[0].id = cudaLaunchAttributeProgrammaticStreamSerialization;
    attr[0].val.programmaticStreamSerializationAllowed = 1;
    cfg.attrs = attr;
    cfg.numAttrs = 1;
    cudaError_t e = cudaLaunchKernelEx(&cfg, mean_kernel, out4);
    if (e != cudaSuccess) {
        mean_kernel<<<n4 / 256, 256>>>(out4);
    }
}